// round 1
// baseline (speedup 1.0000x reference)
#include <cuda_runtime.h>

#define KBLK  8
#define IDIM  96
#define ODIM  96
#define XYTOT 65160
#define XYT   64
#define NTHR  256
#define OT    6
#define JT    4

#define SMEM_BYTES (IDIM*XYT*8 + IDIM*ODIM*16)   // 49152 + 147456 = 196608

__device__ __forceinline__ void fma2(unsigned long long &d, unsigned long long a, unsigned long long b) {
    asm("fma.rn.f32x2 %0, %1, %2, %0;" : "+l"(d) : "l"(a), "l"(b));
}
__device__ __forceinline__ unsigned long long pack2(float x, float y) {
    unsigned long long r;
    asm("mov.b64 %0, {%1, %2};" : "=l"(r) : "f"(x), "f"(y));
    return r;
}

__global__ __launch_bounds__(NTHR, 1)
void cmul_kernel(const float2* __restrict__ inp, const float2* __restrict__ wgt,
                 const float2* __restrict__ bias, float2* __restrict__ out)
{
    extern __shared__ unsigned char smem_raw[];
    float2* sIn = (float2*)smem_raw;                                   // [IDIM][XYT]
    float4* sW  = (float4*)(smem_raw + IDIM*XYT*sizeof(float2));       // [IDIM][ODIM] = (wr,wr,-wi,wi)

    const int k   = blockIdx.y;
    const int xy0 = blockIdx.x * XYT;
    const int tid = threadIdx.x;

    // Stage expanded weights: sW[i*ODIM+o] = (wr, wr, -wi, wi)
    const float2* wk = wgt + (size_t)k * IDIM * ODIM;
    for (int idx = tid; idx < IDIM * ODIM; idx += NTHR) {
        float2 w = wk[idx];
        sW[idx] = make_float4(w.x, w.x, -w.y, w.y);
    }
    // Stage input tile [96 i][64 xy] (zero-pad past XYTOT)
    const float2* ik = inp + (size_t)k * IDIM * XYTOT;
    for (int idx = tid; idx < IDIM * XYT; idx += NTHR) {
        int i  = idx >> 6;
        int c  = idx & 63;
        int xy = xy0 + c;
        float2 v = make_float2(0.f, 0.f);
        if (xy < XYTOT) v = ik[(size_t)i * XYTOT + xy];
        sIn[idx] = v;
    }
    __syncthreads();

    const int ogrp  = tid >> 4;   // 0..15
    const int xygrp = tid & 15;   // 0..15
    const int ob    = ogrp * OT;

    // Accumulators initialized with bias (saves epilogue adds)
    unsigned long long acc[OT][JT];
    const float2* bk = bias + (size_t)k * ODIM;
    #pragma unroll
    for (int o = 0; o < OT; ++o) {
        float2 b = bk[ob + o];
        unsigned long long bb = pack2(b.x, b.y);
        #pragma unroll
        for (int j = 0; j < JT; ++j) acc[o][j] = bb;
    }

    // Main loop: complex MAC via two packed f32x2 FMAs per (i, o, xy)
    //   acc(re,im) += (ar,ai)*(wr,wr)  +  (ai,ar)*(-wi,wi)
    #pragma unroll 4
    for (int i = 0; i < IDIM; ++i) {
        unsigned long long a[JT], as[JT];
        #pragma unroll
        for (int j = 0; j < JT; ++j) {
            float2 v = sIn[i * XYT + xygrp + 16 * j];   // conflict-free LDS.64
            a[j]  = pack2(v.x, v.y);
            as[j] = pack2(v.y, v.x);
        }
        #pragma unroll
        for (int o = 0; o < OT; ++o) {
            const longlong2 w = *(const longlong2*)(sW + i * ODIM + ob + o);  // LDS.128 broadcast
            #pragma unroll
            for (int j = 0; j < JT; ++j) {
                fma2(acc[o][j], a[j],  (unsigned long long)w.x);
                fma2(acc[o][j], as[j], (unsigned long long)w.y);
            }
        }
    }

    // Store (coalesced across the 16 threads sharing an o-group)
    #pragma unroll
    for (int o = 0; o < OT; ++o) {
        float2* orow = out + ((size_t)(k * ODIM + ob + o)) * XYTOT;
        #pragma unroll
        for (int j = 0; j < JT; ++j) {
            int xy = xy0 + xygrp + 16 * j;
            if (xy < XYTOT) {
                float2 r;
                asm("mov.b64 {%0, %1}, %2;" : "=f"(r.x), "=f"(r.y) : "l"(acc[o][j]));
                orow[xy] = r;
            }
        }
    }
}

extern "C" void kernel_launch(void* const* d_in, const int* in_sizes, int n_in,
                              void* d_out, int out_size)
{
    const float2* inp  = (const float2*)d_in[0];
    const float2* wgt  = (const float2*)d_in[1];
    const float2* bias = (const float2*)d_in[2];
    float2* out = (float2*)d_out;

    cudaFuncSetAttribute(cmul_kernel, cudaFuncAttributeMaxDynamicSharedMemorySize, SMEM_BYTES);

    dim3 grid((XYTOT + XYT - 1) / XYT, KBLK);
    cmul_kernel<<<grid, NTHR, SMEM_BYTES>>>(inp, wgt, bias, out);
}

// round 3
// speedup vs baseline: 1.8320x; 1.8320x over previous
#include <cuda_runtime.h>
#include <cuda_bf16.h>
#include <cstdint>

#define KBLK   8
#define IDIM   96
#define ODIM   96
#define XYTOT  65160
#define XYT    128
#define NTHR   256

#define PITCH_B   224                     // bytes per row (56 words; 56 % 32 == 24)
#define A_TILE    (128 * PITCH_B)         // 28672
#define W_TILE    (96  * PITCH_B)         // 21504
#define SM_A      0
#define SM_W      (4 * A_TILE)            // 114688
#define SMEM_TOTAL (SM_W + 4 * W_TILE)    // 200704

// fp32 -> (bf16 hi via truncation, bf16 lo rounded); two values packed per reg
static __device__ __forceinline__ void split2(float a, float b, uint32_t& hi, uint32_t& lo) {
    uint32_t ua = __float_as_uint(a), ub = __float_as_uint(b);
    asm("prmt.b32 %0, %1, %2, 0x7632;" : "=r"(hi) : "r"(ua), "r"(ub));
    float ra = a - __uint_as_float(ua & 0xFFFF0000u);
    float rb = b - __uint_as_float(ub & 0xFFFF0000u);
    asm("cvt.rn.bf16x2.f32 %0, %1, %2;" : "=r"(lo) : "f"(rb), "f"(ra));  // lo half = ra
}

// k-permutation inside each 16-wide block: pair j (i=2j,2j+1) -> word index
static __device__ __forceinline__ int kword(int j) {
    return ((j >> 3) << 3) + ((j & 3) << 1) + ((j >> 2) & 1);
}

#define MMA(c, a, b)                                                            \
    asm volatile("mma.sync.aligned.m16n8k16.row.col.f32.bf16.bf16.f32 "         \
        "{%0,%1,%2,%3},{%4,%5,%6,%7},{%8,%9},{%0,%1,%2,%3};"                    \
        : "+f"((c)[0]), "+f"((c)[1]), "+f"((c)[2]), "+f"((c)[3])                \
        : "r"((a)[0]), "r"((a)[1]), "r"((a)[2]), "r"((a)[3]),                   \
          "r"((b).x), "r"((b).y))

__global__ __launch_bounds__(NTHR, 1)
void cmul_hmma(const float2* __restrict__ inp, const float2* __restrict__ wgt,
               const float2* __restrict__ bias, float2* __restrict__ out)
{
    extern __shared__ unsigned char sm[];
    const int tid = threadIdx.x, lane = tid & 31, wid = tid >> 5;
    const int g = lane >> 2, tig = lane & 3;
    const int kk = blockIdx.y;
    const int xy0 = blockIdx.x * XYT;

    // ---------------- stage A: [xy 128][i 96] -> 4 bf16 tiles ----------------
    {
        const int jg = tig;                 // word-group 0..3
        #pragma unroll
        for (int rr = 0; rr < 16; rr += 8) {
            const int r = wid * 16 + rr + g;
            const int xy = xy0 + r;
            const bool ok = xy < XYTOT;
            const float2* src = inp + (size_t)kk * IDIM * XYTOT + xy;
            #pragma unroll
            for (int t = 0; t < 12; ++t) {
                const int j = jg + 4 * t;               // i-pair index 0..47
                float2 va = ok ? src[(size_t)(2 * j)     * XYTOT] : make_float2(0.f, 0.f);
                float2 vb = ok ? src[(size_t)(2 * j + 1) * XYTOT] : make_float2(0.f, 0.f);
                uint32_t rh, rl, ih, il;
                split2(va.x, vb.x, rh, rl);
                split2(va.y, vb.y, ih, il);
                const uint32_t off = (uint32_t)(r * PITCH_B + kword(j) * 4);
                *(uint32_t*)(sm + SM_A + 0 * A_TILE + off) = rh;
                *(uint32_t*)(sm + SM_A + 1 * A_TILE + off) = rl;
                *(uint32_t*)(sm + SM_A + 2 * A_TILE + off) = ih;
                *(uint32_t*)(sm + SM_A + 3 * A_TILE + off) = il;
            }
        }
    }

    // ---------------- stage W: Wt[o 96][i 96] -> 4 bf16 tiles ----------------
    for (int u = tid; u < 96 * 48; u += NTHR) {
        const int o = u / 48, j = u % 48;
        const float2* src = wgt + (size_t)kk * IDIM * ODIM + o;
        float2 va = src[(size_t)(2 * j)     * ODIM];
        float2 vb = src[(size_t)(2 * j + 1) * ODIM];
        uint32_t rh, rl, ih, il;
        split2(va.x, vb.x, rh, rl);
        split2(va.y, vb.y, ih, il);
        const uint32_t off = (uint32_t)(o * PITCH_B + kword(j) * 4);
        *(uint32_t*)(sm + SM_W + 0 * W_TILE + off) = rh;
        *(uint32_t*)(sm + SM_W + 1 * W_TILE + off) = rl;
        *(uint32_t*)(sm + SM_W + 2 * W_TILE + off) = ih;
        *(uint32_t*)(sm + SM_W + 3 * W_TILE + off) = il;
    }
    __syncthreads();

    // ---------------- MMA phase ----------------
    const int warpM = (wid & 3) * 32;       // xy offset of warp tile
    const int warpN = (wid >> 2) * 48;      // o  offset of warp tile

    float accP1[2][6][4], accP2[2][6][4], accP3[2][6][4];
    #pragma unroll
    for (int mt = 0; mt < 2; ++mt)
        #pragma unroll
        for (int nt = 0; nt < 6; ++nt)
            #pragma unroll
            for (int q = 0; q < 4; ++q) {
                accP1[mt][nt][q] = 0.f; accP2[mt][nt][q] = 0.f; accP3[mt][nt][q] = 0.f;
            }

    // pass tables: (A tile, W tile, acc)  A: 0=ArH 1=ArL 2=AiH 3=AiL ; W: 0=WrH 1=WrL 2=WiH 3=WiL
    const int PA[12] = {0,1,0, 2,3,2, 2,3,2,0,1,0};
    const int PW[12] = {0,0,1, 2,2,3, 0,0,1,2,2,3};
    const int PS[12] = {0,0,0, 1,1,1, 2,2,2,2,2,2};

    const uint32_t aRow = (uint32_t)((warpM + g) * PITCH_B);
    const uint32_t bRow = (uint32_t)((warpN + g) * PITCH_B);

    #pragma unroll 1
    for (int ks = 0; ks < 6; ++ks) {
        const uint32_t koff = (uint32_t)(ks * 32 + tig * 8);
        #pragma unroll
        for (int at = 0; at < 4; ++at) {
            // A fragments for both m-tiles (one LDS.64 per 8-row group)
            uint32_t Af[2][4];
            #pragma unroll
            for (int mt = 0; mt < 2; ++mt) {
                const uint32_t ab = SM_A + at * A_TILE + aRow + mt * (16 * PITCH_B) + koff;
                uint2 lo = *(const uint2*)(sm + ab);
                uint2 hi = *(const uint2*)(sm + ab + 8 * PITCH_B);
                Af[mt][0] = lo.x; Af[mt][1] = hi.x; Af[mt][2] = lo.y; Af[mt][3] = hi.y;
            }
            #pragma unroll
            for (int c = 0; c < 12; ++c) {
                if (PA[c] != at) continue;
                const uint32_t wb = SM_W + PW[c] * W_TILE + bRow + koff;
                #pragma unroll
                for (int nt = 0; nt < 6; ++nt) {
                    const uint2 Bf = *(const uint2*)(sm + wb + nt * (8 * PITCH_B));
                    #pragma unroll
                    for (int mt = 0; mt < 2; ++mt) {
                        if (PS[c] == 0)      { MMA(accP1[mt][nt], Af[mt], Bf); }
                        else if (PS[c] == 1) { MMA(accP2[mt][nt], Af[mt], Bf); }
                        else                 { MMA(accP3[mt][nt], Af[mt], Bf); }
                    }
                }
            }
        }
    }

    // ---------------- epilogue ----------------
    const float2* bk = bias + (size_t)kk * ODIM;
    float2* outk = out + (size_t)kk * ODIM * XYTOT;
    #pragma unroll
    for (int nt = 0; nt < 6; ++nt) {
        const int o0 = warpN + nt * 8 + 2 * tig;
        const float2 b0 = bk[o0], b1 = bk[o0 + 1];
        #pragma unroll
        for (int mt = 0; mt < 2; ++mt) {
            const int xyA = xy0 + warpM + mt * 16 + g;
            const int xyB = xyA + 8;
            if (xyA < XYTOT) {
                outk[(size_t)o0 * XYTOT + xyA] = make_float2(
                    accP1[mt][nt][0] - accP2[mt][nt][0] + b0.x,
                    accP3[mt][nt][0] + b0.y);
                outk[(size_t)(o0 + 1) * XYTOT + xyA] = make_float2(
                    accP1[mt][nt][1] - accP2[mt][nt][1] + b1.x,
                    accP3[mt][nt][1] + b1.y);
            }
            if (xyB < XYTOT) {
                outk[(size_t)o0 * XYTOT + xyB] = make_float2(
                    accP1[mt][nt][2] - accP2[mt][nt][2] + b0.x,
                    accP3[mt][nt][2] + b0.y);
                outk[(size_t)(o0 + 1) * XYTOT + xyB] = make_float2(
                    accP1[mt][nt][3] - accP2[mt][nt][3] + b1.x,
                    accP3[mt][nt][3] + b1.y);
            }
        }
    }
}

extern "C" void kernel_launch(void* const* d_in, const int* in_sizes, int n_in,
                              void* d_out, int out_size)
{
    const float2* inp  = (const float2*)d_in[0];
    const float2* wgt  = (const float2*)d_in[1];
    const float2* bias = (const float2*)d_in[2];
    float2* out = (float2*)d_out;

    cudaFuncSetAttribute(cmul_hmma, cudaFuncAttributeMaxDynamicSharedMemorySize, SMEM_TOTAL);

    dim3 grid((XYTOT + XYT - 1) / XYT, KBLK);
    cmul_hmma<<<grid, NTHR, SMEM_TOTAL>>>(inp, wgt, bias, out);
}

// round 4
// speedup vs baseline: 2.3497x; 1.2826x over previous
#include <cuda_runtime.h>
#include <cuda_bf16.h>
#include <cstdint>

#define KBLK   8
#define IDIM   96
#define ODIM   96
#define XYTOT  65160
#define XYT    64
#define NTHR   256
#define NTILES 1019            // ceil(65160/64)
#define NCHUNK 18

#define PITCH      224         // bytes/row: 48 data words + pad; 56%32==24 -> conflict-free
#define A_TILE     (XYT * PITCH)     // 14336
#define W_TILE     (ODIM * PITCH)    // 21504
#define SM_W       0
#define SM_A       (4 * W_TILE)      // 86016
#define ABUF       (4 * A_TILE)      // 57344
#define SMEM_TOTAL (SM_A + 2 * ABUF) // 200704

// fp32 -> (bf16 hi via truncation, bf16 lo rounded); two values packed per reg
static __device__ __forceinline__ void split2(float a, float b, uint32_t& hi, uint32_t& lo) {
    uint32_t ua = __float_as_uint(a), ub = __float_as_uint(b);
    asm("prmt.b32 %0, %1, %2, 0x7632;" : "=r"(hi) : "r"(ua), "r"(ub));
    float ra = a - __uint_as_float(ua & 0xFFFF0000u);
    float rb = b - __uint_as_float(ub & 0xFFFF0000u);
    asm("cvt.rn.bf16x2.f32 %0, %1, %2;" : "=r"(lo) : "f"(rb), "f"(ra));
}
// k-permutation inside each 16-wide i-block (pair j -> word index)
static __device__ __forceinline__ int kword(int j) {
    return ((j >> 3) << 3) + ((j & 3) << 1) + ((j >> 2) & 1);
}

#define MMA(c, a, b)                                                            \
    asm volatile("mma.sync.aligned.m16n8k16.row.col.f32.bf16.bf16.f32 "         \
        "{%0,%1,%2,%3},{%4,%5,%6,%7},{%8,%9},{%0,%1,%2,%3};"                    \
        : "+f"((c)[0]), "+f"((c)[1]), "+f"((c)[2]), "+f"((c)[3])                \
        : "r"((a)[0]), "r"((a)[1]), "r"((a)[2]), "r"((a)[3]),                   \
          "r"((b).x), "r"((b).y))

__global__ __launch_bounds__(NTHR, 1)
void cmul_pers(const float2* __restrict__ inp, const float2* __restrict__ wgt,
               const float2* __restrict__ bias, float2* __restrict__ out)
{
    extern __shared__ unsigned char sm[];
    const int tid = threadIdx.x, lane = tid & 31, wid = tid >> 5;
    const int g = lane >> 2, tig = lane & 3;
    const int kk = blockIdx.y, chunk = blockIdx.x;

    const int basecnt = NTILES / NCHUNK;          // 56
    const int rem     = NTILES - basecnt * NCHUNK; // 11
    const int cnt     = basecnt + (chunk < rem ? 1 : 0);
    const int t0      = chunk * basecnt + (chunk < rem ? chunk : rem);

    // ---------------- stage W once: Wt[o][i] -> 4 bf16 tiles ----------------
    for (int u = tid; u < 96 * 48; u += NTHR) {
        const int o = u / 48, j = u % 48;
        const float2* src = wgt + (size_t)kk * IDIM * ODIM + o;
        float2 wa = src[(size_t)(2 * j)     * ODIM];
        float2 wb = src[(size_t)(2 * j + 1) * ODIM];
        uint32_t rh, rl, ih, il;
        split2(wa.x, wb.x, rh, rl);
        split2(wa.y, wb.y, ih, il);
        const uint32_t off = (uint32_t)(o * PITCH + kword(j) * 4);
        *(uint32_t*)(sm + SM_W + 0 * W_TILE + off) = rh;
        *(uint32_t*)(sm + SM_W + 1 * W_TILE + off) = rl;
        *(uint32_t*)(sm + SM_W + 2 * W_TILE + off) = ih;
        *(uint32_t*)(sm + SM_W + 3 * W_TILE + off) = il;
    }

    const int warpM = (wid & 1) * 32;
    const int warpN = (wid >> 1) * 24;

    // bias in registers
    float2 bv0[3], bv1[3];
    #pragma unroll
    for (int nt = 0; nt < 3; ++nt) {
        const int o0 = warpN + nt * 8 + 2 * tig;
        bv0[nt] = bias[kk * ODIM + o0];
        bv1[nt] = bias[kk * ODIM + o0 + 1];
    }

    const int jg  = tid >> 6;   // 0..3 (i-pair group)
    const int xyl = tid & 63;   // local xy row
    const float2* aink = inp + (size_t)kk * IDIM * XYTOT;
    float2* outk = out + (size_t)kk * ODIM * XYTOT;

    float2 va[12], vb[12];

    // ---------------- prologue: LDG + stage tile t0 into buf0 ----------------
    {
        const int xy = t0 * XYT + xyl;
        const bool ok = xy < XYTOT;
        const float2* s = aink + xy;
        #pragma unroll
        for (int q = 0; q < 12; ++q) {
            const int j = jg + 4 * q;
            va[q] = ok ? s[(size_t)(2 * j)     * XYTOT] : make_float2(0.f, 0.f);
            vb[q] = ok ? s[(size_t)(2 * j + 1) * XYTOT] : make_float2(0.f, 0.f);
        }
        #pragma unroll
        for (int q = 0; q < 12; ++q) {
            const int j = jg + 4 * q;
            uint32_t rh, rl, ih, il;
            split2(va[q].x, vb[q].x, rh, rl);
            split2(va[q].y, vb[q].y, ih, il);
            const uint32_t off = SM_A + (uint32_t)(xyl * PITCH + kword(j) * 4);
            *(uint32_t*)(sm + off + 0 * A_TILE) = rh;
            *(uint32_t*)(sm + off + 1 * A_TILE) = rl;
            *(uint32_t*)(sm + off + 2 * A_TILE) = ih;
            *(uint32_t*)(sm + off + 3 * A_TILE) = il;
        }
    }
    __syncthreads();

    // pass tables (folded at compile time by full unroll)
    const int PA[12] = {0,1,0, 2,3,2, 2,3,2,0,1,0};   // A: 0=ArH 1=ArL 2=AiH 3=AiL
    const int PW[12] = {0,0,1, 2,2,3, 0,0,1,2,2,3};   // W: 0=WrH 1=WrL 2=WiH 3=WiL
    const int PS[12] = {0,0,0, 1,1,1, 2,2,2,2,2,2};   // acc: P1,P2,P3

    #pragma unroll 1
    for (int t = 0; t < cnt; ++t) {
        const int buf = t & 1;
        const bool hasNext = (t + 1) < cnt;

        // issue next tile's LDGs (complete during MMA)
        if (hasNext) {
            const int xy = (t0 + t + 1) * XYT + xyl;
            const bool ok = xy < XYTOT;
            const float2* s = aink + xy;
            #pragma unroll
            for (int q = 0; q < 12; ++q) {
                const int j = jg + 4 * q;
                va[q] = ok ? s[(size_t)(2 * j)     * XYTOT] : make_float2(0.f, 0.f);
                vb[q] = ok ? s[(size_t)(2 * j + 1) * XYTOT] : make_float2(0.f, 0.f);
            }
        }

        float acc[3][2][3][4];
        #pragma unroll
        for (int p = 0; p < 3; ++p)
            #pragma unroll
            for (int mt = 0; mt < 2; ++mt)
                #pragma unroll
                for (int nt = 0; nt < 3; ++nt)
                    #pragma unroll
                    for (int q = 0; q < 4; ++q) acc[p][mt][nt][q] = 0.f;

        const uint32_t aBase = SM_A + buf * ABUF + (uint32_t)((warpM + g) * PITCH);

        #pragma unroll 1
        for (int ks = 0; ks < 6; ++ks) {
            const uint32_t koff = (uint32_t)(ks * 32 + tig * 8);
            uint32_t Af[4][2][4];
            #pragma unroll
            for (int at = 0; at < 4; ++at)
                #pragma unroll
                for (int mt = 0; mt < 2; ++mt) {
                    const uint32_t ad = aBase + at * A_TILE + mt * (16 * PITCH) + koff;
                    uint2 lo = *(const uint2*)(sm + ad);
                    uint2 hi = *(const uint2*)(sm + ad + 8 * PITCH);
                    Af[at][mt][0] = lo.x; Af[at][mt][1] = hi.x;
                    Af[at][mt][2] = lo.y; Af[at][mt][3] = hi.y;
                }
            uint2 Bf[4][3];
            #pragma unroll
            for (int wt = 0; wt < 4; ++wt)
                #pragma unroll
                for (int nt = 0; nt < 3; ++nt)
                    Bf[wt][nt] = *(const uint2*)(sm + SM_W + wt * W_TILE +
                                  (uint32_t)((warpN + nt * 8 + g) * PITCH) + koff);
            #pragma unroll
            for (int c = 0; c < 12; ++c)
                #pragma unroll
                for (int nt = 0; nt < 3; ++nt)
                    #pragma unroll
                    for (int mt = 0; mt < 2; ++mt)
                        MMA(acc[PS[c]][mt][nt], Af[PA[c]][mt], Bf[PW[c]][nt]);
        }

        // stage next tile into the other buffer
        if (hasNext) {
            const uint32_t sb = SM_A + (1 - buf) * ABUF + (uint32_t)(xyl * PITCH);
            #pragma unroll
            for (int q = 0; q < 12; ++q) {
                const int j = jg + 4 * q;
                uint32_t rh, rl, ih, il;
                split2(va[q].x, vb[q].x, rh, rl);
                split2(va[q].y, vb[q].y, ih, il);
                const uint32_t off = sb + (uint32_t)(kword(j) * 4);
                *(uint32_t*)(sm + off + 0 * A_TILE) = rh;
                *(uint32_t*)(sm + off + 1 * A_TILE) = rl;
                *(uint32_t*)(sm + off + 2 * A_TILE) = ih;
                *(uint32_t*)(sm + off + 3 * A_TILE) = il;
            }
        }

        // epilogue for tile t
        {
            const int xyb = (t0 + t) * XYT + warpM;
            #pragma unroll
            for (int nt = 0; nt < 3; ++nt) {
                const int o0 = warpN + nt * 8 + 2 * tig;
                #pragma unroll
                for (int mt = 0; mt < 2; ++mt) {
                    const int xyA = xyb + mt * 16 + g;
                    const int xyB = xyA + 8;
                    if (xyA < XYTOT) {
                        outk[(size_t)o0 * XYTOT + xyA] = make_float2(
                            acc[0][mt][nt][0] - acc[1][mt][nt][0] + bv0[nt].x,
                            acc[2][mt][nt][0] + bv0[nt].y);
                        outk[(size_t)(o0 + 1) * XYTOT + xyA] = make_float2(
                            acc[0][mt][nt][1] - acc[1][mt][nt][1] + bv1[nt].x,
                            acc[2][mt][nt][1] + bv1[nt].y);
                    }
                    if (xyB < XYTOT) {
                        outk[(size_t)o0 * XYTOT + xyB] = make_float2(
                            acc[0][mt][nt][2] - acc[1][mt][nt][2] + bv0[nt].x,
                            acc[2][mt][nt][2] + bv0[nt].y);
                        outk[(size_t)(o0 + 1) * XYTOT + xyB] = make_float2(
                            acc[0][mt][nt][3] - acc[1][mt][nt][3] + bv1[nt].x,
                            acc[2][mt][nt][3] + bv1[nt].y);
                    }
                }
            }
        }
        __syncthreads();
    }
}

extern "C" void kernel_launch(void* const* d_in, const int* in_sizes, int n_in,
                              void* d_out, int out_size)
{
    const float2* inp  = (const float2*)d_in[0];
    const float2* wgt  = (const float2*)d_in[1];
    const float2* bias = (const float2*)d_in[2];
    float2* out = (float2*)d_out;

    cudaFuncSetAttribute(cmul_pers, cudaFuncAttributeMaxDynamicSharedMemorySize, SMEM_TOTAL);

    dim3 grid(NCHUNK, KBLK);
    cmul_pers<<<grid, NTHR, SMEM_TOTAL>>>(inp, wgt, bias, out);
}

// round 8
// speedup vs baseline: 2.6483x; 1.1271x over previous
#include <cuda_runtime.h>
#include <cuda_bf16.h>
#include <cstdint>

#define KBLK   8
#define IDIM   96
#define ODIM   96
#define XYTOT  65160
#define XYH    (XYTOT/2)
#define XYT    64
#define NTHR   320
#define NCON   256
#define NTILES 1019
#define NCHUNK 18

#define PITCH      224
#define A_TILE     (XYT * PITCH)         // 14336
#define ABUF       (4 * A_TILE)          // 57344
#define W_TILE     (ODIM * PITCH)        // 21504
#define SM_BAR     0                     // full0,full1 @0,8 ; empty0,empty1 @16,24
#define SM_A       1024
#define SM_W       (SM_A + 2 * ABUF)     // 115712
#define SMEM_TOTAL (SM_W + 4 * W_TILE)   // 201728

static __device__ __forceinline__ void split2(float a, float b, uint32_t& hi, uint32_t& lo) {
    uint32_t ua = __float_as_uint(a), ub = __float_as_uint(b);
    asm("prmt.b32 %0, %1, %2, 0x7632;" : "=r"(hi) : "r"(ua), "r"(ub));
    float ra = a - __uint_as_float(ua & 0xFFFF0000u);
    float rb = b - __uint_as_float(ub & 0xFFFF0000u);
    asm("cvt.rn.bf16x2.f32 %0, %1, %2;" : "=r"(lo) : "f"(rb), "f"(ra));
}
static __device__ __forceinline__ int kword(int j) {
    return ((j >> 3) << 3) + ((j & 3) << 1) + ((j >> 2) & 1);
}
static __device__ __forceinline__ uint32_t smem_u32(const void* p) {
    uint32_t a;
    asm("{ .reg .u64 t; cvta.to.shared.u64 t, %1; cvt.u32.u64 %0, t; }" : "=r"(a) : "l"(p));
    return a;
}
static __device__ __forceinline__ void mbar_wait(uint32_t addr, int parity) {
    asm volatile(
        "{ .reg .pred P;\n\t"
        "WL%=: mbarrier.try_wait.parity.acquire.cta.shared::cta.b64 P, [%0], %1, 0x989680;\n\t"
        "@P bra WD%=;\n\t"
        "bra WL%=;\n\t"
        "WD%=: }"
        :: "r"(addr), "r"((uint32_t)parity) : "memory");
}
static __device__ __forceinline__ void mbar_arrive(uint32_t addr) {
    asm volatile("mbarrier.arrive.shared.b64 _, [%0];" :: "r"(addr) : "memory");
}

#define MMA(c, a, b)                                                            \
    asm volatile("mma.sync.aligned.m16n8k16.row.col.f32.bf16.bf16.f32 "         \
        "{%0,%1,%2,%3},{%4,%5,%6,%7},{%8,%9},{%0,%1,%2,%3};"                    \
        : "+f"((c)[0]), "+f"((c)[1]), "+f"((c)[2]), "+f"((c)[3])                \
        : "r"((a)[0]), "r"((a)[1]), "r"((a)[2]), "r"((a)[3]),                   \
          "r"((b).x), "r"((b).y))

// unit u (0..383): p = u/12 (xy-pair), h = u%12 -> b = h>>1 (16-i block), f = h&1 (half)
static __device__ __forceinline__ void prod_load(float4* v, const float4* s4, int u, int xy0) {
    const int p = u / 12, h = u % 12, b = h >> 1, f = h & 1;
    const int i0 = b * 16 + f * 4;
    const bool ok = (xy0 + 2 * p) < XYTOT;
    const size_t g4 = (size_t)(xy0 >> 1) + p;
    #pragma unroll
    for (int q = 0; q < 4; ++q) {
        v[q]     = ok ? __ldg(&s4[(size_t)(i0 + q)     * XYH + g4]) : make_float4(0.f,0.f,0.f,0.f);
        v[4 + q] = ok ? __ldg(&s4[(size_t)(i0 + 8 + q) * XYH + g4]) : make_float4(0.f,0.f,0.f,0.f);
    }
}
static __device__ __forceinline__ void prod_store(unsigned char* sm, const float4* v,
                                                  int u, uint32_t abase) {
    const int p = u / 12, h = u % 12, b = h >> 1, f = h & 1;
    const uint32_t chunk = (uint32_t)(b * 32 + f * 16);
    uint4 RH, RL, IH, IL;
    // xy = 2p  (components .x=re, .y=im)
    split2(v[0].x, v[1].x, RH.x, RL.x);  split2(v[4].x, v[5].x, RH.y, RL.y);
    split2(v[2].x, v[3].x, RH.z, RL.z);  split2(v[6].x, v[7].x, RH.w, RL.w);
    split2(v[0].y, v[1].y, IH.x, IL.x);  split2(v[4].y, v[5].y, IH.y, IL.y);
    split2(v[2].y, v[3].y, IH.z, IL.z);  split2(v[6].y, v[7].y, IH.w, IL.w);
    uint32_t off = abase + (uint32_t)(2 * p) * PITCH + chunk;
    *(uint4*)(sm + off + 0 * A_TILE) = RH;
    *(uint4*)(sm + off + 1 * A_TILE) = RL;
    *(uint4*)(sm + off + 2 * A_TILE) = IH;
    *(uint4*)(sm + off + 3 * A_TILE) = IL;
    // xy = 2p+1 (components .z=re, .w=im)
    split2(v[0].z, v[1].z, RH.x, RL.x);  split2(v[4].z, v[5].z, RH.y, RL.y);
    split2(v[2].z, v[3].z, RH.z, RL.z);  split2(v[6].z, v[7].z, RH.w, RL.w);
    split2(v[0].w, v[1].w, IH.x, IL.x);  split2(v[4].w, v[5].w, IH.y, IL.y);
    split2(v[2].w, v[3].w, IH.z, IL.z);  split2(v[6].w, v[7].w, IH.w, IL.w);
    off += PITCH;
    *(uint4*)(sm + off + 0 * A_TILE) = RH;
    *(uint4*)(sm + off + 1 * A_TILE) = RL;
    *(uint4*)(sm + off + 2 * A_TILE) = IH;
    *(uint4*)(sm + off + 3 * A_TILE) = IL;
}

__global__ __launch_bounds__(NTHR, 1)
void cmul_ws(const float2* __restrict__ inp, const float2* __restrict__ wgt,
             const float2* __restrict__ bias, float2* __restrict__ out)
{
    extern __shared__ unsigned char sm[];
    const uint32_t smb = smem_u32(sm);
    const int tid = threadIdx.x, lane = tid & 31, wid = tid >> 5;
    const int kk = blockIdx.y, chunk = blockIdx.x;

    const int basecnt = NTILES / NCHUNK;
    const int rem     = NTILES - basecnt * NCHUNK;
    const int cnt     = basecnt + (chunk < rem ? 1 : 0);
    const int t0      = chunk * basecnt + (chunk < rem ? chunk : rem);

    if (tid == 0) {
        asm volatile("mbarrier.init.shared.b64 [%0], %1;" :: "r"(smb + 0),  "r"(64u)  : "memory");
        asm volatile("mbarrier.init.shared.b64 [%0], %1;" :: "r"(smb + 8),  "r"(64u)  : "memory");
        asm volatile("mbarrier.init.shared.b64 [%0], %1;" :: "r"(smb + 16), "r"(256u) : "memory");
        asm volatile("mbarrier.init.shared.b64 [%0], %1;" :: "r"(smb + 24), "r"(256u) : "memory");
    }

    // ---- stage W once (all threads): Wt[o][i] -> 4 bf16 tiles ----
    for (int u = tid; u < 96 * 48; u += NTHR) {
        const int o = u / 48, j = u % 48;
        const float2* src = wgt + (size_t)kk * IDIM * ODIM + o;
        float2 wa = src[(size_t)(2 * j)     * ODIM];
        float2 wb = src[(size_t)(2 * j + 1) * ODIM];
        uint32_t rh, rl, ih, il;
        split2(wa.x, wb.x, rh, rl);
        split2(wa.y, wb.y, ih, il);
        const uint32_t off = (uint32_t)(o * PITCH + kword(j) * 4);
        *(uint32_t*)(sm + SM_W + 0 * W_TILE + off) = rh;
        *(uint32_t*)(sm + SM_W + 1 * W_TILE + off) = rl;
        *(uint32_t*)(sm + SM_W + 2 * W_TILE + off) = ih;
        *(uint32_t*)(sm + SM_W + 3 * W_TILE + off) = il;
    }
    __syncthreads();

    if (tid >= NCON) {
        // ================= PRODUCER (warps 8,9; 64 threads) =================
        const int ptid = tid - NCON;
        const float4* s4 = (const float4*)(inp + (size_t)kk * IDIM * XYTOT);
        int phe0 = 1, phe1 = 1;
        float4 v0[8], v1[8];
        #pragma unroll 1
        for (int t = 0; t < cnt; ++t) {
            const int buf = t & 1;
            const int xy0 = (t0 + t) * XYT;
            const uint32_t abase = SM_A + buf * ABUF;
            prod_load(v0, s4, ptid,      xy0);
            prod_load(v1, s4, ptid + 64, xy0);
            if (buf == 0) { mbar_wait(smb + 16, phe0); phe0 ^= 1; }
            else          { mbar_wait(smb + 24, phe1); phe1 ^= 1; }
            prod_store(sm, v0, ptid,       abase); prod_load(v0, s4, ptid + 128, xy0);
            prod_store(sm, v1, ptid + 64,  abase); prod_load(v1, s4, ptid + 192, xy0);
            prod_store(sm, v0, ptid + 128, abase); prod_load(v0, s4, ptid + 256, xy0);
            prod_store(sm, v1, ptid + 192, abase); prod_load(v1, s4, ptid + 320, xy0);
            prod_store(sm, v0, ptid + 256, abase);
            prod_store(sm, v1, ptid + 320, abase);
            mbar_arrive(smb + buf * 8);  // full[buf]
        }
    } else {
        // ================= CONSUMER (warps 0-7; 256 threads) =================
        const int g = lane >> 2, tig = lane & 3;
        const int warpM = (wid & 1) * 32;
        const int warpN = (wid >> 1) * 24;

        float2 bv0[3], bv1[3];
        #pragma unroll
        for (int nt = 0; nt < 3; ++nt) {
            const int o0 = warpN + nt * 8 + 2 * tig;
            bv0[nt] = bias[kk * ODIM + o0];
            bv1[nt] = bias[kk * ODIM + o0 + 1];
        }
        float2* outk = out + (size_t)kk * ODIM * XYTOT;

        const int PA[12] = {0,1,0, 2,3,2, 2,3,2,0,1,0};
        const int PW[12] = {0,0,1, 2,2,3, 0,0,1,2,2,3};
        const int PS[12] = {0,0,0, 1,1,1, 2,2,2,2,2,2};

        int phf0 = 0, phf1 = 0;
        #pragma unroll 1
        for (int t = 0; t < cnt; ++t) {
            const int buf = t & 1;
            if (buf == 0) { mbar_wait(smb + 0, phf0); phf0 ^= 1; }
            else          { mbar_wait(smb + 8, phf1); phf1 ^= 1; }

            float acc[3][2][3][4];
            #pragma unroll
            for (int p = 0; p < 3; ++p)
                #pragma unroll
                for (int mt = 0; mt < 2; ++mt)
                    #pragma unroll
                    for (int nt = 0; nt < 3; ++nt)
                        #pragma unroll
                        for (int q = 0; q < 4; ++q) acc[p][mt][nt][q] = 0.f;

            const uint32_t aBase = SM_A + buf * ABUF + (uint32_t)((warpM + g) * PITCH);

            #pragma unroll 1
            for (int ks = 0; ks < 6; ++ks) {
                const uint32_t koff = (uint32_t)(ks * 32 + tig * 8);
                uint32_t Af[4][2][4];
                #pragma unroll
                for (int at = 0; at < 4; ++at)
                    #pragma unroll
                    for (int mt = 0; mt < 2; ++mt) {
                        const uint32_t ad = aBase + at * A_TILE + mt * (16 * PITCH) + koff;
                        uint2 lo = *(const uint2*)(sm + ad);
                        uint2 hi = *(const uint2*)(sm + ad + 8 * PITCH);
                        Af[at][mt][0] = lo.x; Af[at][mt][1] = hi.x;
                        Af[at][mt][2] = lo.y; Af[at][mt][3] = hi.y;
                    }
                uint2 Bf[4][3];
                #pragma unroll
                for (int wt = 0; wt < 4; ++wt)
                    #pragma unroll
                    for (int nt = 0; nt < 3; ++nt)
                        Bf[wt][nt] = *(const uint2*)(sm + SM_W + wt * W_TILE +
                                      (uint32_t)((warpN + nt * 8 + g) * PITCH) + koff);
                #pragma unroll
                for (int c = 0; c < 12; ++c)
                    #pragma unroll
                    for (int nt = 0; nt < 3; ++nt)
                        #pragma unroll
                        for (int mt = 0; mt < 2; ++mt)
                            MMA(acc[PS[c]][mt][nt], Af[PA[c]][mt], Bf[PW[c]][nt]);
            }

            // release buffer before epilogue (acc is register-resident)
            mbar_arrive(smb + 16 + buf * 8);  // empty[buf]

            const int xyb = (t0 + t) * XYT + warpM;
            #pragma unroll
            for (int nt = 0; nt < 3; ++nt) {
                const int o0 = warpN + nt * 8 + 2 * tig;
                #pragma unroll
                for (int mt = 0; mt < 2; ++mt) {
                    const int xyA = xyb + mt * 16 + g;
                    const int xyB = xyA + 8;
                    if (xyA < XYTOT) {
                        outk[(size_t)o0 * XYTOT + xyA] = make_float2(
                            acc[0][mt][nt][0] - acc[1][mt][nt][0] + bv0[nt].x,
                            acc[2][mt][nt][0] + bv0[nt].y);
                        outk[(size_t)(o0 + 1) * XYTOT + xyA] = make_float2(
                            acc[0][mt][nt][1] - acc[1][mt][nt][1] + bv1[nt].x,
                            acc[2][mt][nt][1] + bv1[nt].y);
                    }
                    if (xyB < XYTOT) {
                        outk[(size_t)o0 * XYTOT + xyB] = make_float2(
                            acc[0][mt][nt][2] - acc[1][mt][nt][2] + bv0[nt].x,
                            acc[2][mt][nt][2] + bv0[nt].y);
                        outk[(size_t)(o0 + 1) * XYTOT + xyB] = make_float2(
                            acc[0][mt][nt][3] - acc[1][mt][nt][3] + bv1[nt].x,
                            acc[2][mt][nt][3] + bv1[nt].y);
                    }
                }
            }
        }
    }
}

extern "C" void kernel_launch(void* const* d_in, const int* in_sizes, int n_in,
                              void* d_out, int out_size)
{
    const float2* inp  = (const float2*)d_in[0];
    const float2* wgt  = (const float2*)d_in[1];
    const float2* bias = (const float2*)d_in[2];
    float2* out = (float2*)d_out;

    cudaFuncSetAttribute(cmul_ws, cudaFuncAttributeMaxDynamicSharedMemorySize, SMEM_TOTAL);

    dim3 grid(NCHUNK, KBLK);
    cmul_ws<<<grid, NTHR, SMEM_TOTAL>>>(inp, wgt, bias, out);
}